// round 16
// baseline (speedup 1.0000x reference)
#include <cuda_runtime.h>
#include <cuda_bf16.h>
#include <cstdint>

#define N_ATOMS 100000
#define E_ATOMS 200000
#define N_AMINO 10240
#define E_AMINO 20480
#define BGRAPH  512
#define D_IN    40
#define D_E     11
#define H       20
#define D_AA    8
#define F_IN    28
#define H_ARMA  128
#define K_ST    3
#define T_LAY   7
#define F1      256
#define F2      128
#define F3      64
#define NCOMB   260     // 220 (z) + 20 (xb) + 20 (root-init)
#define ZCOLS   240     // bf16 part: z (220) + xb (20)
#define ACOLS   32      // fp32 acc part (20 used, padded)

// ------------------------- scratch (device globals) -------------------------
__device__ __nv_bfloat16 g_zb[(long)N_ATOMS * ZCOLS];
__device__ float g_acn1[(long)N_ATOMS * ACOLS];
__device__ float g_acn2[(long)N_ATOMS * ACOLS];
__device__ float g_wpack[3][D_IN * NCOMB];
__device__ float g_bpack[3][NCOMB];
__device__ float g_aa[N_AMINO * F_IN];
__device__ float g_norm[E_AMINO];
__device__ float g_tmp [K_ST * N_AMINO * H_ARMA];
__device__ float g_accA[K_ST * N_AMINO * H_ARMA];
__device__ float g_accB[K_ST * N_AMINO * H_ARMA];
__device__ float g_rootterm[(long)T_LAY * K_ST * N_AMINO * H_ARMA];
__device__ int g_off_am[N_AMINO + 1];
__device__ int g_list_am[E_AMINO];
__device__ int g_start[BGRAPH + 1];

// ------------------------- tf32 helpers -------------------------
__device__ __forceinline__ float f2tf32(float x) {
    uint32_t u;
    asm("cvt.rna.tf32.f32 %0, %1;" : "=r"(u) : "f"(x));
    return __uint_as_float(u);
}

__device__ __forceinline__ void mma_tf32(float c[4], const float a[4], const float bb[2]) {
    asm volatile(
        "mma.sync.aligned.m16n8k8.row.col.f32.tf32.tf32.f32 "
        "{%0,%1,%2,%3}, {%4,%5,%6,%7}, {%8,%9}, {%0,%1,%2,%3};\n"
        : "+f"(c[0]), "+f"(c[1]), "+f"(c[2]), "+f"(c[3])
        : "r"(__float_as_uint(a[0])), "r"(__float_as_uint(a[1])),
          "r"(__float_as_uint(a[2])), "r"(__float_as_uint(a[3])),
          "r"(__float_as_uint(bb[0])), "r"(__float_as_uint(bb[1])));
}

// ------------------------- NNConv node GEMM, compile-time K, single stage ----
// grid.y = 4 (cols 0..255 only); cols 256..259 handled by nnconv_tail.
template<int KD, int KDP, int SAS, int KSTEPS>
__global__ void __launch_bounds__(256, 5) nnconv_gemm_t(
        const float* __restrict__ A, int lda,
        const float* __restrict__ W,
        const float* __restrict__ Bias,
        __nv_bfloat16* __restrict__ zb,
        float* __restrict__ acc,
        int M, int reluA)
{
    const int N = NCOMB;
    __shared__ float sA[128][SAS];
    __shared__ float sW[KDP][72];

    int m0 = blockIdx.x * 128;
    int n0 = blockIdx.y * 64;
    int tid = threadIdx.x;
    int warp = tid >> 5, lane = tid & 31;
    int wm = warp >> 1, wn = warp & 1;
    int gid = lane >> 2, tig = lane & 3;

    const int AQ = KDP / 4;
    #pragma unroll
    for (int i = 0; i < (128 * AQ + 255) / 256; i++) {
        int idx = tid + i * 256;
        if (idx < 128 * AQ) {
            int m  = idx / AQ;
            int c  = (idx - m * AQ) * 4;
            int row = m0 + m;
            float4 a = make_float4(0.f, 0.f, 0.f, 0.f);
            if (row < M && c < KD)
                a = *(const float4*)(A + (long)row * lda + c);
            if (reluA) {
                a.x = fmaxf(a.x, 0.f); a.y = fmaxf(a.y, 0.f);
                a.z = fmaxf(a.z, 0.f); a.w = fmaxf(a.w, 0.f);
            }
            a.x = f2tf32(a.x); a.y = f2tf32(a.y);
            a.z = f2tf32(a.z); a.w = f2tf32(a.w);
            *(float4*)(&sA[m][c]) = a;
        }
    }
    #pragma unroll
    for (int i = 0; i < (KDP * 16 + 255) / 256; i++) {
        int idx = tid + i * 256;
        if (idx < KDP * 16) {
            int kg = idx >> 4;
            int nn = (idx & 15) << 2;
            int n  = n0 + nn;
            float4 w = make_float4(0.f, 0.f, 0.f, 0.f);
            if (kg < KD)
                w = *(const float4*)(W + (long)kg * N + n);   // n <= 252, always valid
            w.x = f2tf32(w.x); w.y = f2tf32(w.y);
            w.z = f2tf32(w.z); w.w = f2tf32(w.w);
            *(float4*)(&sW[kg][nn]) = w;
        }
    }
    __syncthreads();

    float c[2][4][4];
    #pragma unroll
    for (int mt = 0; mt < 2; mt++)
        #pragma unroll
        for (int nt = 0; nt < 4; nt++)
            #pragma unroll
            for (int q = 0; q < 4; q++) c[mt][nt][q] = 0.f;

    #pragma unroll
    for (int ks = 0; ks < KSTEPS; ks++) {
        int kb = ks * 8;
        float afr[2][4], bfr[4][2];
        #pragma unroll
        for (int mt = 0; mt < 2; mt++) {
            int r = wm * 32 + mt * 16;
            afr[mt][0] = sA[r + gid    ][kb + tig];
            afr[mt][1] = sA[r + gid + 8][kb + tig];
            afr[mt][2] = sA[r + gid    ][kb + tig + 4];
            afr[mt][3] = sA[r + gid + 8][kb + tig + 4];
        }
        #pragma unroll
        for (int nt = 0; nt < 4; nt++) {
            int cc = wn * 32 + nt * 8 + gid;
            bfr[nt][0] = sW[kb + tig    ][cc];
            bfr[nt][1] = sW[kb + tig + 4][cc];
        }
        #pragma unroll
        for (int mt = 0; mt < 2; mt++)
            #pragma unroll
            for (int nt = 0; nt < 4; nt++)
                mma_tf32(c[mt][nt], afr[mt], bfr[nt]);
    }

    #pragma unroll
    for (int mt = 0; mt < 2; mt++) {
        #pragma unroll
        for (int nt = 0; nt < 4; nt++) {
            int col = n0 + wn * 32 + nt * 8 + 2 * tig;   // <= 254
            float bv0 = Bias[col], bv1 = Bias[col + 1];
            #pragma unroll
            for (int half = 0; half < 2; half++) {
                int row = m0 + wm * 32 + mt * 16 + gid + half * 8;
                if (row >= M) continue;
                float v0 = c[mt][nt][half * 2]     + bv0;
                float v1 = c[mt][nt][half * 2 + 1] + bv1;
                if (col < ZCOLS) {
                    __nv_bfloat162 hv = __floats2bfloat162_rn(v0, v1);
                    *(__nv_bfloat162*)(zb + (long)row * ZCOLS + col) = hv;
                } else {
                    *(float2*)(acc + (long)row * ACOLS + (col - ZCOLS)) =
                        make_float2(v0, v1);
                }
            }
        }
    }
}

// ------------------------- NNConv tail: packed cols 256..259 (acc cols 16..19)
template<int KD>
__global__ void nnconv_tail(const float* __restrict__ A, int lda,
                            const float* __restrict__ W,
                            const float* __restrict__ Bias,
                            float* __restrict__ acc, int M, int reluA)
{
    int row = blockIdx.x * blockDim.x + threadIdx.x;
    if (row >= M) return;
    float s0 = Bias[256], s1 = Bias[257], s2 = Bias[258], s3 = Bias[259];
    const float* ar = A + (long)row * lda;
    #pragma unroll
    for (int k = 0; k < KD; k++) {
        float a = ar[k];
        if (reluA) a = fmaxf(a, 0.f);
        a = f2tf32(a);
        const float* wr = W + (long)k * NCOMB + 256;
        s0 = fmaf(a, f2tf32(wr[0]), s0);
        s1 = fmaf(a, f2tf32(wr[1]), s1);
        s2 = fmaf(a, f2tf32(wr[2]), s2);
        s3 = fmaf(a, f2tf32(wr[3]), s3);
    }
    *(float4*)(acc + (long)row * ACOLS + 16) = make_float4(s0, s1, s2, s3);
}

// ------------------------- ARMA tf32 GEMM, BN=64, compile-time K, opt bias ---
template<int KDT, int KDP, int RELU>
__global__ void __launch_bounds__(256) arma_gemm_t(
        const float* __restrict__ A, int lda, long strideA,
        const float* __restrict__ W, long strideW,
        const float* __restrict__ Bias, long strideB,
        float* __restrict__ C)
{
    __shared__ float sA[128][36];
    __shared__ float sW[32][72];

    int bz = blockIdx.z;
    const float* Ab = A + (long)bz * strideA;
    const float* Wb = W + (long)bz * strideW;
    float*       Cb = C + (long)bz * (long)N_AMINO * H_ARMA;
    int m0 = blockIdx.x * 128;
    int n0 = blockIdx.y * 64;
    int tid = threadIdx.x;
    int warp = tid >> 5, lane = tid & 31;
    int wm = warp >> 1, wn = warp & 1;
    int gid = lane >> 2, tig = lane & 3;

    float c[2][4][4];
    #pragma unroll
    for (int mt = 0; mt < 2; mt++)
        #pragma unroll
        for (int nt = 0; nt < 4; nt++)
            #pragma unroll
            for (int q = 0; q < 4; q++) c[mt][nt][q] = 0.f;

    #pragma unroll
    for (int c0 = 0; c0 < KDP; c0 += 32) {
        #pragma unroll
        for (int i = 0; i < 4; i++) {
            int idx = tid + i * 256;
            int m  = idx >> 3;
            int kk = (idx & 7) << 2;
            int kg = c0 + kk;
            float4 a = make_float4(0.f, 0.f, 0.f, 0.f);
            if (kg + 3 < KDT || (KDT % 32 == 0))
                a = *(const float4*)(Ab + (long)(m0 + m) * lda + kg);
            if (RELU) {
                a.x = fmaxf(a.x, 0.f); a.y = fmaxf(a.y, 0.f);
                a.z = fmaxf(a.z, 0.f); a.w = fmaxf(a.w, 0.f);
            }
            a.x = f2tf32(a.x); a.y = f2tf32(a.y);
            a.z = f2tf32(a.z); a.w = f2tf32(a.w);
            *(float4*)(&sA[m][kk]) = a;
        }
        #pragma unroll
        for (int i = 0; i < 2; i++) {
            int idx = tid + i * 256;
            int kk = idx >> 4;
            int nn = (idx & 15) << 2;
            int kg = c0 + kk;
            float4 w = make_float4(0.f, 0.f, 0.f, 0.f);
            if (kg < KDT || (KDT % 32 == 0))
                w = *(const float4*)(Wb + (long)kg * H_ARMA + n0 + nn);
            w.x = f2tf32(w.x); w.y = f2tf32(w.y);
            w.z = f2tf32(w.z); w.w = f2tf32(w.w);
            *(float4*)(&sW[kk][nn]) = w;
        }
        __syncthreads();

        #pragma unroll
        for (int ks = 0; ks < 4; ks++) {
            int kb = ks * 8;
            float afr[2][4], bfr[4][2];
            #pragma unroll
            for (int mt = 0; mt < 2; mt++) {
                int r = wm * 32 + mt * 16;
                afr[mt][0] = sA[r + gid    ][kb + tig];
                afr[mt][1] = sA[r + gid + 8][kb + tig];
                afr[mt][2] = sA[r + gid    ][kb + tig + 4];
                afr[mt][3] = sA[r + gid + 8][kb + tig + 4];
            }
            #pragma unroll
            for (int nt = 0; nt < 4; nt++) {
                int cc = wn * 32 + nt * 8 + gid;
                bfr[nt][0] = sW[kb + tig    ][cc];
                bfr[nt][1] = sW[kb + tig + 4][cc];
            }
            #pragma unroll
            for (int mt = 0; mt < 2; mt++)
                #pragma unroll
                for (int nt = 0; nt < 4; nt++)
                    mma_tf32(c[mt][nt], afr[mt], bfr[nt]);
        }
        __syncthreads();
    }

    #pragma unroll
    for (int mt = 0; mt < 2; mt++) {
        #pragma unroll
        for (int nt = 0; nt < 4; nt++) {
            int row = m0 + wm * 32 + mt * 16 + gid;
            int col = n0 + wn * 32 + nt * 8 + 2 * tig;
            float bv0 = 0.f, bv1 = 0.f;
            if (Bias) {
                bv0 = Bias[(long)bz * strideB + col];
                bv1 = Bias[(long)bz * strideB + col + 1];
            }
            *(float2*)(Cb + (long)row * H_ARMA + col) =
                make_float2(c[mt][nt][0] + bv0, c[mt][nt][1] + bv1);
            *(float2*)(Cb + (long)(row + 8) * H_ARMA + col) =
                make_float2(c[mt][nt][2] + bv0, c[mt][nt][3] + bv1);
        }
    }
}

// ------------------------- ARMA tf32 GEMM K=128, BN=128 (one N tile) ---------
__global__ void __launch_bounds__(256) arma_gemm128(
        const float* __restrict__ A, long strideA,
        const float* __restrict__ W, long strideW,
        float* __restrict__ C)
{
    __shared__ float sA[128][36];
    __shared__ float sW[32][136];

    int bz = blockIdx.z;
    const float* Ab = A + (long)bz * strideA;
    const float* Wb = W + (long)bz * strideW;
    float*       Cb = C + (long)bz * (long)N_AMINO * H_ARMA;
    int m0 = blockIdx.x * 128;
    int tid = threadIdx.x;
    int warp = tid >> 5, lane = tid & 31;
    int wm = warp >> 2, wn = warp & 3;
    int gid = lane >> 2, tig = lane & 3;

    float c[4][4][4];
    #pragma unroll
    for (int mt = 0; mt < 4; mt++)
        #pragma unroll
        for (int nt = 0; nt < 4; nt++)
            #pragma unroll
            for (int q = 0; q < 4; q++) c[mt][nt][q] = 0.f;

    #pragma unroll
    for (int c0 = 0; c0 < 128; c0 += 32) {
        #pragma unroll
        for (int i = 0; i < 4; i++) {
            int idx = tid + i * 256;
            int m  = idx >> 3;
            int kk = (idx & 7) << 2;
            float4 a = *(const float4*)(Ab + (long)(m0 + m) * H_ARMA + c0 + kk);
            a.x = fmaxf(a.x, 0.f); a.y = fmaxf(a.y, 0.f);
            a.z = fmaxf(a.z, 0.f); a.w = fmaxf(a.w, 0.f);
            a.x = f2tf32(a.x); a.y = f2tf32(a.y);
            a.z = f2tf32(a.z); a.w = f2tf32(a.w);
            *(float4*)(&sA[m][kk]) = a;
        }
        #pragma unroll
        for (int i = 0; i < 4; i++) {
            int idx = tid + i * 256;
            int kk = idx >> 5;
            int nn = (idx & 31) << 2;
            float4 w = *(const float4*)(Wb + (long)(c0 + kk) * H_ARMA + nn);
            w.x = f2tf32(w.x); w.y = f2tf32(w.y);
            w.z = f2tf32(w.z); w.w = f2tf32(w.w);
            *(float4*)(&sW[kk][nn]) = w;
        }
        __syncthreads();

        #pragma unroll
        for (int ks = 0; ks < 4; ks++) {
            int kb = ks * 8;
            float afr[4][4], bfr[4][2];
            #pragma unroll
            for (int mt = 0; mt < 4; mt++) {
                int r = wm * 64 + mt * 16;
                afr[mt][0] = sA[r + gid    ][kb + tig];
                afr[mt][1] = sA[r + gid + 8][kb + tig];
                afr[mt][2] = sA[r + gid    ][kb + tig + 4];
                afr[mt][3] = sA[r + gid + 8][kb + tig + 4];
            }
            #pragma unroll
            for (int nt = 0; nt < 4; nt++) {
                int cc = wn * 32 + nt * 8 + gid;
                bfr[nt][0] = sW[kb + tig    ][cc];
                bfr[nt][1] = sW[kb + tig + 4][cc];
            }
            #pragma unroll
            for (int mt = 0; mt < 4; mt++)
                #pragma unroll
                for (int nt = 0; nt < 4; nt++)
                    mma_tf32(c[mt][nt], afr[mt], bfr[nt]);
        }
        __syncthreads();
    }

    #pragma unroll
    for (int mt = 0; mt < 4; mt++) {
        #pragma unroll
        for (int nt = 0; nt < 4; nt++) {
            int row = m0 + wm * 64 + mt * 16 + gid;
            int col = wn * 32 + nt * 8 + 2 * tig;
            *(float2*)(Cb + (long)row * H_ARMA + col) =
                make_float2(c[mt][nt][0], c[mt][nt][1]);
            *(float2*)(Cb + (long)(row + 8) * H_ARMA + col) =
                make_float2(c[mt][nt][2], c[mt][nt][3]);
        }
    }
}

// ------------------------- prep: amino CSR + norm + starts + aa feature init -------------------------
__global__ void prep_k(const int* __restrict__ aeiSrc, const int* __restrict__ aeiDst,
                       const int* __restrict__ ab, const float* __restrict__ feat,
                       int* __restrict__ offM, int* __restrict__ listM,
                       float* __restrict__ nrm, int* __restrict__ startp,
                       float* __restrict__ aa)
{
    extern __shared__ int sh[];
    int* cnt  = sh;
    int* cur  = sh + N_AMINO;
    int* part = sh + 2 * N_AMINO;
    int tid = threadIdx.x;

    for (int idx = tid; idx < N_AMINO * F_IN; idx += 1024) {
        int n = idx / F_IN, c = idx - n * F_IN;
        aa[idx] = (c < H) ? 0.f : feat[n * D_AA + (c - H)];
    }

    for (int i = tid; i < N_AMINO; i += 1024) cnt[i] = 0;
    __syncthreads();
    for (int e = tid; e < E_AMINO; e += 1024) atomicAdd(&cnt[aeiDst[e]], 1);
    __syncthreads();
    for (int e = tid; e < E_AMINO; e += 1024) {
        int s = aeiSrc[e], d = aeiDst[e];
        int cs = cnt[s], cd = cnt[d];
        float a = cs > 0 ? rsqrtf((float)cs) : 0.f;
        float c = cd > 0 ? rsqrtf((float)cd) : 0.f;
        nrm[e] = a * c;
    }
    __syncthreads();
    int base = tid * 10;
    int loc[10];
    int s = 0;
    #pragma unroll
    for (int j = 0; j < 10; j++) { loc[j] = cnt[base + j]; s += loc[j]; }
    part[tid] = s;
    __syncthreads();
    for (int off = 1; off < 1024; off <<= 1) {
        int v = part[tid];
        int o = (tid >= off) ? part[tid - off] : 0;
        __syncthreads();
        part[tid] = v + o;
        __syncthreads();
    }
    int run = part[tid] - s;
    #pragma unroll
    for (int j = 0; j < 10; j++) {
        int cc = loc[j];
        cnt[base + j] = run;
        cur[base + j] = run;
        run += cc;
    }
    __syncthreads();
    for (int i = tid; i < N_AMINO; i += 1024) offM[i] = cnt[i];
    if (tid == 0) offM[N_AMINO] = E_AMINO;
    for (int e = tid; e < E_AMINO; e += 1024) {
        int p = atomicAdd(&cur[aeiDst[e]], 1);
        listM[p] = e;
    }
    for (int n = tid; n < N_AMINO; n += 1024) {
        int bv = ab[n];
        int prev = (n == 0) ? -1 : ab[n - 1];
        for (int g = prev + 1; g <= bv; g++) startp[g] = n;
        if (n == N_AMINO - 1)
            for (int g = bv + 1; g <= BGRAPH; g++) startp[g] = N_AMINO;
    }
}

// ------------------------- weight packing -------------------------
__global__ void pack3_k(const float* __restrict__ nw1, const float* __restrict__ nb1,
                        const float* __restrict__ r1,  const float* __restrict__ bb1,
                        const float* __restrict__ nw2, const float* __restrict__ nb2,
                        const float* __restrict__ r2,  const float* __restrict__ bb2,
                        const float* __restrict__ nw3, const float* __restrict__ nb3,
                        const float* __restrict__ r3,  const float* __restrict__ bb3,
                        float* __restrict__ Wp, float* __restrict__ bp)
{
    int layer = blockIdx.y;
    const float *nw, *nb, *root, *b;
    int d_in;
    if (layer == 0)      { nw = nw1; nb = nb1; root = r1; b = bb1; d_in = D_IN; }
    else if (layer == 1) { nw = nw2; nb = nb2; root = r2; b = bb2; d_in = H; }
    else                 { nw = nw3; nb = nb3; root = r3; b = bb3; d_in = H; }
    float* W   = Wp + layer * D_IN * NCOMB;
    float* bpp = bp + layer * NCOMB;

    int idx = blockIdx.x * blockDim.x + threadIdx.x;
    int total = d_in * NCOMB;
    if (idx < total) {
        int i = idx / NCOMB, c = idx % NCOMB;
        float v;
        if (c < 220)      { int d = c / H, o = c % H; v = nw[d * (d_in * H) + i * H + o]; }
        else if (c < 240) { v = nb[i * H + (c - 220)]; }
        else              { v = root[i * H + (c - 240)]; }
        W[idx] = v;
    }
    if (idx < NCOMB) bpp[idx] = (idx < 240) ? 0.f : b[idx - 240];
}

// ------------------------- NNConv edge aggregation (bf16x2, 2 outputs/thread) -----
__global__ void nnconv_edge(const int* __restrict__ ei, const float* __restrict__ ea,
                            const __nv_bfloat16* __restrict__ zb,
                            float* __restrict__ acc)
{
    long idx = (long)blockIdx.x * blockDim.x + threadIdx.x;
    if (idx >= (long)E_ATOMS * (H / 2)) return;
    int e  = (int)(idx / (H / 2));
    int o2 = (int)(idx % (H / 2));
    int o  = o2 * 2;
    int src = ei[e], dst = ei[E_ATOMS + e];
    const __nv_bfloat162* zrow2 =
        (const __nv_bfloat162*)(zb + (long)src * ZCOLS);
    float2 m = __bfloat1622float2(zrow2[110 + o2]);   // xb pair (cols 220..)
    const float* eav = ea + (long)e * D_E;
    #pragma unroll
    for (int d = 0; d < D_E; d++) {
        float2 z = __bfloat1622float2(zrow2[d * (H / 2) + o2]);
        float w = eav[d];
        m.x = fmaf(w, z.x, m.x);
        m.y = fmaf(w, z.y, m.y);
    }
    float* dstp = acc + (long)dst * ACOLS + o;
    atomicAdd(dstp,     m.x);
    atomicAdd(dstp + 1, m.y);
}

// ------------------------- atoms -> amino -------------------------
__global__ void atom2aa(const float* __restrict__ acc, const int* __restrict__ lab,
                        float* __restrict__ aa)
{
    long idx = (long)blockIdx.x * blockDim.x + threadIdx.x;
    if (idx >= (long)N_ATOMS * H) return;
    int n = (int)(idx / H), o = (int)(idx % H);
    float v = fmaxf(acc[(long)n * ACOLS + o], 0.f);
    atomicAdd(&aa[lab[n] * F_IN + o], v);
}

// slim ARMA gather: acc = rootterm[t] + gather(nrm * tmp), float4 per thread
__global__ void arma_gather(const float* __restrict__ rt,
                            const int* __restrict__ off, const int* __restrict__ list,
                            const int* __restrict__ aeiSrc, const float* __restrict__ nrm,
                            const float* __restrict__ tmp, float* __restrict__ acc)
{
    int idx = blockIdx.x * blockDim.x + threadIdx.x;
    const int O4 = H_ARMA / 4;
    if (idx >= K_ST * N_AMINO * O4) return;
    int o = (idx & (O4 - 1)) << 2;
    int r = idx >> 5;
    int n = r % N_AMINO;
    int k = r / N_AMINO;

    float4 s = *(const float4*)(rt + 4 * (long)idx);

    long kb = (long)k * N_AMINO;
    int p0 = off[n], p1 = off[n + 1];
    for (int p = p0; p < p1; p++) {
        int e = list[p];
        float nv = nrm[e];
        float4 t = *(const float4*)(tmp + (kb + aeiSrc[e]) * H_ARMA + o);
        s.x = fmaf(nv, t.x, s.x);
        s.y = fmaf(nv, t.y, s.y);
        s.z = fmaf(nv, t.z, s.z);
        s.w = fmaf(nv, t.w, s.w);
    }
    *(float4*)(acc + ((kb + n) * H_ARMA + o)) = s;
}

// ------------------------- fused head: pool + 4 FC layers -------------------------
__global__ void __launch_bounds__(256) head_fused(
        const float* __restrict__ acc, const int* __restrict__ start,
        const float* __restrict__ l1_w, const float* __restrict__ l1_b,
        const float* __restrict__ l2_w, const float* __restrict__ l2_b,
        const float* __restrict__ l3_w, const float* __restrict__ l3_b,
        const float* __restrict__ l4_w, const float* __restrict__ l4_b,
        float* __restrict__ out)
{
    __shared__ float pool[H_ARMA];
    __shared__ float h1[F1];
    __shared__ float h2[F2];
    __shared__ float h3[F3];
    int b = blockIdx.x;
    int tid = threadIdx.x;

    if (tid < H_ARMA) {
        int n0 = start[b], n1 = start[b + 1];
        float s = 0.f;
        for (int n = n0; n < n1; n++) {
            #pragma unroll
            for (int k = 0; k < K_ST; k++)
                s += fmaxf(acc[((long)k * N_AMINO + n) * H_ARMA + tid], 0.f);
        }
        pool[tid] = s * (1.f / 3.f);
    }
    __syncthreads();
    {
        float s = l1_b[tid];
        #pragma unroll 4
        for (int f = 0; f < H_ARMA; f++)
            s = fmaf(pool[f], l1_w[f * F1 + tid], s);
        h1[tid] = fmaxf(s, 0.f);
    }
    __syncthreads();
    if (tid < F2) {
        float s = l2_b[tid];
        #pragma unroll 4
        for (int f = 0; f < F1; f++)
            s = fmaf(h1[f], l2_w[f * F2 + tid], s);
        h2[tid] = fmaxf(s, 0.f);
    }
    __syncthreads();
    if (tid < F3) {
        float s = l3_b[tid];
        #pragma unroll 4
        for (int f = 0; f < F2; f++)
            s = fmaf(h2[f], l3_w[f * F3 + tid], s);
        h3[tid] = fmaxf(s, 0.f);
    }
    __syncthreads();
    if (tid == 0) {
        float s = l4_b[0];
        #pragma unroll
        for (int f = 0; f < F3; f++) s = fmaf(h3[f], l4_w[f], s);
        out[b] = s;
    }
}

// ------------------------- host orchestration -------------------------
static inline int ceil_div(long a, int b) { return (int)((a + b - 1) / b); }

extern "C" void kernel_launch(void* const* d_in, const int* in_sizes, int n_in,
                              void* d_out, int out_size)
{
    const float* x     = (const float*)d_in[0];
    const int*   ei    = (const int*)  d_in[1];
    const float* ea    = (const float*)d_in[2];
    const int*   lab   = (const int*)  d_in[3];
    const float* feat  = (const float*)d_in[4];
    const int*   aei   = (const int*)  d_in[5];
    const int*   ab    = (const int*)  d_in[6];
    const float* nn1_w = (const float*)d_in[7];
    const float* nn1_b = (const float*)d_in[8];
    const float* root1 = (const float*)d_in[9];
    const float* b1    = (const float*)d_in[10];
    const float* nn2_w = (const float*)d_in[11];
    const float* nn2_b = (const float*)d_in[12];
    const float* root2 = (const float*)d_in[13];
    const float* b2    = (const float*)d_in[14];
    const float* nn3_w = (const float*)d_in[15];
    const float* nn3_b = (const float*)d_in[16];
    const float* root3 = (const float*)d_in[17];
    const float* b3    = (const float*)d_in[18];
    const float* arma_init = (const float*)d_in[19];
    const float* arma_w    = (const float*)d_in[20];
    const float* arma_root = (const float*)d_in[21];
    const float* arma_bias = (const float*)d_in[22];
    const float* l1_w = (const float*)d_in[23];
    const float* l1_b = (const float*)d_in[24];
    const float* l2_w = (const float*)d_in[25];
    const float* l2_b = (const float*)d_in[26];
    const float* l3_w = (const float*)d_in[27];
    const float* l3_b = (const float*)d_in[28];
    const float* l4_w = (const float*)d_in[29];
    const float* l4_b = (const float*)d_in[30];

    float *wp, *bp, *aa, *nrm, *tmp, *accA, *accB, *acn1, *acn2, *rtp;
    __nv_bfloat16* zb;
    int *offM, *listM, *startp;
    cudaGetSymbolAddress((void**)&zb,   g_zb);
    cudaGetSymbolAddress((void**)&acn1, g_acn1);
    cudaGetSymbolAddress((void**)&acn2, g_acn2);
    cudaGetSymbolAddress((void**)&wp,   g_wpack);
    cudaGetSymbolAddress((void**)&bp,   g_bpack);
    cudaGetSymbolAddress((void**)&aa,   g_aa);
    cudaGetSymbolAddress((void**)&nrm,  g_norm);
    cudaGetSymbolAddress((void**)&tmp,  g_tmp);
    cudaGetSymbolAddress((void**)&accA, g_accA);
    cudaGetSymbolAddress((void**)&accB, g_accB);
    cudaGetSymbolAddress((void**)&rtp,  g_rootterm);
    cudaGetSymbolAddress((void**)&offM, g_off_am);
    cudaGetSymbolAddress((void**)&listM, g_list_am);
    cudaGetSymbolAddress((void**)&startp, g_start);

    static bool attr_set = false;
    if (!attr_set) {
        cudaFuncSetAttribute(prep_k, cudaFuncAttributeMaxDynamicSharedMemorySize,
                             (2 * N_AMINO + 1024) * sizeof(int));
        attr_set = true;
    }

    const int TB = 256;
    const int* aeiSrc = aei;
    const int* aeiDst = aei + E_AMINO;

    dim3 gN1(ceil_div(N_ATOMS, 128), 4, 1);   // cols 0..255 (tail kernel covers 256..259)
    int tailBlocks = ceil_div(N_ATOMS, TB);
    int edgeBlocks = ceil_div((long)E_ATOMS * (H / 2), TB);

    // pack + prep
    dim3 gPack(ceil_div(D_IN * NCOMB, TB), 3);
    pack3_k<<<gPack, TB>>>(nn1_w, nn1_b, root1, b1,
                           nn2_w, nn2_b, root2, b2,
                           nn3_w, nn3_b, root3, b3, wp, bp);
    prep_k<<<1, 1024, (2 * N_AMINO + 1024) * sizeof(int)>>>(
        aeiSrc, aeiDst, ab, feat, offM, listM, nrm, startp, aa);

    // NNConv layers (main GEMM y=4 + tail cols + edge aggregation)
    nnconv_gemm_t<40, 40, 44, 5><<<gN1, 256>>>(x, D_IN, wp, bp, zb, acn1, N_ATOMS, 0);
    nnconv_tail<40><<<tailBlocks, TB>>>(x, D_IN, wp, bp, acn1, N_ATOMS, 0);
    nnconv_edge<<<edgeBlocks, TB>>>(ei, ea, zb, acn1);

    nnconv_gemm_t<20, 24, 24, 3><<<gN1, 256>>>(acn1, ACOLS, wp + D_IN * NCOMB, bp + NCOMB,
                                               zb, acn2, N_ATOMS, 1);
    nnconv_tail<20><<<tailBlocks, TB>>>(acn1, ACOLS, wp + D_IN * NCOMB, bp + NCOMB,
                                        acn2, N_ATOMS, 1);
    nnconv_edge<<<edgeBlocks, TB>>>(ei, ea, zb, acn2);

    nnconv_gemm_t<20, 24, 24, 3><<<gN1, 256>>>(acn2, ACOLS, wp + 2 * D_IN * NCOMB, bp + 2 * NCOMB,
                                               zb, acn1, N_ATOMS, 1);
    nnconv_tail<20><<<tailBlocks, TB>>>(acn2, ACOLS, wp + 2 * D_IN * NCOMB, bp + 2 * NCOMB,
                                        acn1, N_ATOMS, 1);
    nnconv_edge<<<edgeBlocks, TB>>>(ei, ea, zb, acn1);

    // atoms -> amino
    atom2aa<<<ceil_div((long)N_ATOMS * H, TB), TB>>>(acn1, lab, aa);

    // precompute ALL 21 root terms: rootterm[t][k] = aa @ root[t][k] + bias[t][k]
    dim3 gRoot(N_AMINO / 128, H_ARMA / 64, T_LAY * K_ST);   // (80, 2, 21)
    arma_gemm_t<28, 32, 0><<<gRoot, 256>>>(
        aa, F_IN, 0,
        arma_root, (long)F_IN * H_ARMA,
        arma_bias, H_ARMA,
        rtp);

    // ARMA: K=3 stacks, T=7 layers (GEMM + slim gather per layer)
    dim3 gArma64(N_AMINO / 128, H_ARMA / 64, K_ST);   // (80, 2, 3)
    dim3 gArma128(N_AMINO / 128, 1, K_ST);            // (80, 1, 3)
    int gatherBlocks = ceil_div(K_ST * N_AMINO * (H_ARMA / 4), TB);
    float* accP = accA;
    float* accN = accB;
    for (int t = 0; t < T_LAY; t++) {
        if (t == 0) {
            arma_gemm_t<28, 32, 0><<<gArma64, 256>>>(
                aa, F_IN, 0,
                arma_init, (long)F_IN * H_ARMA,
                nullptr, 0,
                tmp);
        } else {
            arma_gemm128<<<gArma128, 256>>>(
                accP, (long)N_AMINO * H_ARMA,
                arma_w + (long)(t - 1) * K_ST * H_ARMA * H_ARMA, (long)H_ARMA * H_ARMA,
                tmp);
        }
        arma_gather<<<gatherBlocks, TB>>>(
            rtp + (long)t * K_ST * N_AMINO * H_ARMA,
            offM, listM, aeiSrc, nrm, tmp, accN);
        float* t2 = accP; accP = accN; accN = t2;
    }

    // fused head: pool + FC stack
    head_fused<<<BGRAPH, 256>>>(accP, startp,
                                l1_w, l1_b, l2_w, l2_b, l3_w, l3_b, l4_w, l4_b,
                                (float*)d_out);
}

// round 17
// speedup vs baseline: 1.0550x; 1.0550x over previous
#include <cuda_runtime.h>
#include <cuda_bf16.h>
#include <cstdint>

#define N_ATOMS 100000
#define E_ATOMS 200000
#define N_AMINO 10240
#define E_AMINO 20480
#define BGRAPH  512
#define D_IN    40
#define D_E     11
#define H       20
#define D_AA    8
#define F_IN    28
#define H_ARMA  128
#define K_ST    3
#define T_LAY   7
#define F1      256
#define F2      128
#define F3      64
#define NCOMB   260     // 220 (z) + 20 (xb) + 20 (root-init)
#define ZCOLS   240     // bf16 part: z (220) + xb (20)
#define ACOLS   32      // fp32 acc part (20 used, padded)

// ------------------------- scratch (device globals) -------------------------
__device__ __nv_bfloat16 g_zb[(long)N_ATOMS * ZCOLS];
__device__ float g_acn1[(long)N_ATOMS * ACOLS];
__device__ float g_acn2[(long)N_ATOMS * ACOLS];
__device__ float g_wpack[3][D_IN * NCOMB];
__device__ float g_bpack[3][NCOMB];
__device__ float g_aa[N_AMINO * F_IN];
__device__ float g_norm[E_AMINO];
__device__ float g_tmp [K_ST * N_AMINO * H_ARMA];
__device__ float g_accA[K_ST * N_AMINO * H_ARMA];
__device__ float g_accB[K_ST * N_AMINO * H_ARMA];
__device__ float g_rootterm[(long)T_LAY * K_ST * N_AMINO * H_ARMA];
__device__ int g_off_am[N_AMINO + 1];
__device__ int g_list_am[E_AMINO];
__device__ int g_start[BGRAPH + 1];

// ------------------------- tf32 helpers -------------------------
__device__ __forceinline__ float f2tf32(float x) {
    uint32_t u;
    asm("cvt.rna.tf32.f32 %0, %1;" : "=r"(u) : "f"(x));
    return __uint_as_float(u);
}

__device__ __forceinline__ void mma_tf32(float c[4], const float a[4], const float bb[2]) {
    asm volatile(
        "mma.sync.aligned.m16n8k8.row.col.f32.tf32.tf32.f32 "
        "{%0,%1,%2,%3}, {%4,%5,%6,%7}, {%8,%9}, {%0,%1,%2,%3};\n"
        : "+f"(c[0]), "+f"(c[1]), "+f"(c[2]), "+f"(c[3])
        : "r"(__float_as_uint(a[0])), "r"(__float_as_uint(a[1])),
          "r"(__float_as_uint(a[2])), "r"(__float_as_uint(a[3])),
          "r"(__float_as_uint(bb[0])), "r"(__float_as_uint(bb[1])));
}

// ------------------------- NNConv node GEMM, compile-time K, single stage ----
template<int KD, int KDP, int SAS, int KSTEPS>
__global__ void __launch_bounds__(256, 5) nnconv_gemm_t(
        const float* __restrict__ A, int lda,
        const float* __restrict__ W,
        const float* __restrict__ Bias,
        __nv_bfloat16* __restrict__ zb,
        float* __restrict__ acc,
        int M, int reluA)
{
    const int N = NCOMB;
    __shared__ float sA[128][SAS];
    __shared__ float sW[KDP][72];

    int m0 = blockIdx.x * 128;
    int n0 = blockIdx.y * 64;
    int tid = threadIdx.x;
    int warp = tid >> 5, lane = tid & 31;
    int wm = warp >> 1, wn = warp & 1;
    int gid = lane >> 2, tig = lane & 3;

    const int AQ = KDP / 4;
    #pragma unroll
    for (int i = 0; i < (128 * AQ + 255) / 256; i++) {
        int idx = tid + i * 256;
        if (idx < 128 * AQ) {
            int m  = idx / AQ;
            int c  = (idx - m * AQ) * 4;
            int row = m0 + m;
            float4 a = make_float4(0.f, 0.f, 0.f, 0.f);
            if (row < M && c < KD)
                a = *(const float4*)(A + (long)row * lda + c);
            if (reluA) {
                a.x = fmaxf(a.x, 0.f); a.y = fmaxf(a.y, 0.f);
                a.z = fmaxf(a.z, 0.f); a.w = fmaxf(a.w, 0.f);
            }
            a.x = f2tf32(a.x); a.y = f2tf32(a.y);
            a.z = f2tf32(a.z); a.w = f2tf32(a.w);
            *(float4*)(&sA[m][c]) = a;
        }
    }
    #pragma unroll
    for (int i = 0; i < (KDP * 16 + 255) / 256; i++) {
        int idx = tid + i * 256;
        if (idx < KDP * 16) {
            int kg = idx >> 4;
            int nn = (idx & 15) << 2;
            int n  = n0 + nn;
            float4 w = make_float4(0.f, 0.f, 0.f, 0.f);
            if (kg < KD) {
                const float* wr = W + (long)kg * N;
                if (n + 3 < N) w = *(const float4*)(wr + n);
                else {
                    if (n     < N) w.x = wr[n];
                    if (n + 1 < N) w.y = wr[n + 1];
                    if (n + 2 < N) w.z = wr[n + 2];
                    if (n + 3 < N) w.w = wr[n + 3];
                }
            }
            w.x = f2tf32(w.x); w.y = f2tf32(w.y);
            w.z = f2tf32(w.z); w.w = f2tf32(w.w);
            *(float4*)(&sW[kg][nn]) = w;
        }
    }
    __syncthreads();

    float c[2][4][4];
    #pragma unroll
    for (int mt = 0; mt < 2; mt++)
        #pragma unroll
        for (int nt = 0; nt < 4; nt++)
            #pragma unroll
            for (int q = 0; q < 4; q++) c[mt][nt][q] = 0.f;

    #pragma unroll
    for (int ks = 0; ks < KSTEPS; ks++) {
        int kb = ks * 8;
        float afr[2][4], bfr[4][2];
        #pragma unroll
        for (int mt = 0; mt < 2; mt++) {
            int r = wm * 32 + mt * 16;
            afr[mt][0] = sA[r + gid    ][kb + tig];
            afr[mt][1] = sA[r + gid + 8][kb + tig];
            afr[mt][2] = sA[r + gid    ][kb + tig + 4];
            afr[mt][3] = sA[r + gid + 8][kb + tig + 4];
        }
        #pragma unroll
        for (int nt = 0; nt < 4; nt++) {
            int cc = wn * 32 + nt * 8 + gid;
            bfr[nt][0] = sW[kb + tig    ][cc];
            bfr[nt][1] = sW[kb + tig + 4][cc];
        }
        #pragma unroll
        for (int mt = 0; mt < 2; mt++)
            #pragma unroll
            for (int nt = 0; nt < 4; nt++)
                mma_tf32(c[mt][nt], afr[mt], bfr[nt]);
    }

    #pragma unroll
    for (int mt = 0; mt < 2; mt++) {
        #pragma unroll
        for (int nt = 0; nt < 4; nt++) {
            int col = n0 + wn * 32 + nt * 8 + 2 * tig;
            if (col + 1 >= N) continue;
            float bv0 = Bias[col], bv1 = Bias[col + 1];
            #pragma unroll
            for (int half = 0; half < 2; half++) {
                int row = m0 + wm * 32 + mt * 16 + gid + half * 8;
                if (row >= M) continue;
                float v0 = c[mt][nt][half * 2]     + bv0;
                float v1 = c[mt][nt][half * 2 + 1] + bv1;
                if (col < ZCOLS) {
                    __nv_bfloat162 hv = __floats2bfloat162_rn(v0, v1);
                    *(__nv_bfloat162*)(zb + (long)row * ZCOLS + col) = hv;
                } else {
                    *(float2*)(acc + (long)row * ACOLS + (col - ZCOLS)) =
                        make_float2(v0, v1);
                }
            }
        }
    }
}

// ------------------------- combined K=28 ARMA GEMM (root terms + t=0 init) ---
// grid.z = 24: z in [0,21) -> rtp[z] = aa @ root[z] + bias[z]
//              z in [21,24) -> tmp[z-21] = aa @ init[z-21]
__global__ void __launch_bounds__(256) arma_gemm28_comb(
        const float* __restrict__ aa,
        const float* __restrict__ arma_root,   // [21][F_IN][H_ARMA]
        const float* __restrict__ arma_bias,   // [21][H_ARMA]
        const float* __restrict__ arma_init,   // [3][F_IN][H_ARMA]
        float* __restrict__ rtp,               // [21][N_AMINO][H_ARMA]
        float* __restrict__ tmp)               // [3][N_AMINO][H_ARMA]
{
    __shared__ float sA[128][36];
    __shared__ float sW[32][72];

    int bz = blockIdx.z;
    const float* Wb;
    const float* Bias;
    float* Cb;
    if (bz < T_LAY * K_ST) {
        Wb = arma_root + (long)bz * F_IN * H_ARMA;
        Bias = arma_bias + (long)bz * H_ARMA;
        Cb = rtp + (long)bz * N_AMINO * H_ARMA;
    } else {
        Wb = arma_init + (long)(bz - T_LAY * K_ST) * F_IN * H_ARMA;
        Bias = nullptr;
        Cb = tmp + (long)(bz - T_LAY * K_ST) * N_AMINO * H_ARMA;
    }
    int m0 = blockIdx.x * 128;
    int n0 = blockIdx.y * 64;
    int tid = threadIdx.x;
    int warp = tid >> 5, lane = tid & 31;
    int wm = warp >> 1, wn = warp & 1;
    int gid = lane >> 2, tig = lane & 3;

    float c[2][4][4];
    #pragma unroll
    for (int mt = 0; mt < 2; mt++)
        #pragma unroll
        for (int nt = 0; nt < 4; nt++)
            #pragma unroll
            for (int q = 0; q < 4; q++) c[mt][nt][q] = 0.f;

    // single K chunk: K=28 pad 32
    #pragma unroll
    for (int i = 0; i < 4; i++) {
        int idx = tid + i * 256;
        int m  = idx >> 3;
        int kk = (idx & 7) << 2;
        float4 a = make_float4(0.f, 0.f, 0.f, 0.f);
        if (kk + 3 < F_IN)
            a = *(const float4*)(aa + (long)(m0 + m) * F_IN + kk);
        a.x = f2tf32(a.x); a.y = f2tf32(a.y);
        a.z = f2tf32(a.z); a.w = f2tf32(a.w);
        *(float4*)(&sA[m][kk]) = a;
    }
    #pragma unroll
    for (int i = 0; i < 2; i++) {
        int idx = tid + i * 256;
        int kk = idx >> 4;
        int nn = (idx & 15) << 2;
        float4 w = make_float4(0.f, 0.f, 0.f, 0.f);
        if (kk < F_IN)
            w = *(const float4*)(Wb + (long)kk * H_ARMA + n0 + nn);
        w.x = f2tf32(w.x); w.y = f2tf32(w.y);
        w.z = f2tf32(w.z); w.w = f2tf32(w.w);
        *(float4*)(&sW[kk][nn]) = w;
    }
    __syncthreads();

    #pragma unroll
    for (int ks = 0; ks < 4; ks++) {
        int kb = ks * 8;
        float afr[2][4], bfr[4][2];
        #pragma unroll
        for (int mt = 0; mt < 2; mt++) {
            int r = wm * 32 + mt * 16;
            afr[mt][0] = sA[r + gid    ][kb + tig];
            afr[mt][1] = sA[r + gid + 8][kb + tig];
            afr[mt][2] = sA[r + gid    ][kb + tig + 4];
            afr[mt][3] = sA[r + gid + 8][kb + tig + 4];
        }
        #pragma unroll
        for (int nt = 0; nt < 4; nt++) {
            int cc = wn * 32 + nt * 8 + gid;
            bfr[nt][0] = sW[kb + tig    ][cc];
            bfr[nt][1] = sW[kb + tig + 4][cc];
        }
        #pragma unroll
        for (int mt = 0; mt < 2; mt++)
            #pragma unroll
            for (int nt = 0; nt < 4; nt++)
                mma_tf32(c[mt][nt], afr[mt], bfr[nt]);
    }

    #pragma unroll
    for (int mt = 0; mt < 2; mt++) {
        #pragma unroll
        for (int nt = 0; nt < 4; nt++) {
            int row = m0 + wm * 32 + mt * 16 + gid;
            int col = n0 + wn * 32 + nt * 8 + 2 * tig;
            float bv0 = 0.f, bv1 = 0.f;
            if (Bias) {
                bv0 = Bias[col];
                bv1 = Bias[col + 1];
            }
            *(float2*)(Cb + (long)row * H_ARMA + col) =
                make_float2(c[mt][nt][0] + bv0, c[mt][nt][1] + bv1);
            *(float2*)(Cb + (long)(row + 8) * H_ARMA + col) =
                make_float2(c[mt][nt][2] + bv0, c[mt][nt][3] + bv1);
        }
    }
}

// ------------------------- ARMA tf32 GEMM K=128, BN=128 (one N tile) ---------
__global__ void __launch_bounds__(256) arma_gemm128(
        const float* __restrict__ A, long strideA,
        const float* __restrict__ W, long strideW,
        float* __restrict__ C)
{
    __shared__ float sA[128][36];
    __shared__ float sW[32][136];

    int bz = blockIdx.z;
    const float* Ab = A + (long)bz * strideA;
    const float* Wb = W + (long)bz * strideW;
    float*       Cb = C + (long)bz * (long)N_AMINO * H_ARMA;
    int m0 = blockIdx.x * 128;
    int tid = threadIdx.x;
    int warp = tid >> 5, lane = tid & 31;
    int wm = warp >> 2, wn = warp & 3;
    int gid = lane >> 2, tig = lane & 3;

    float c[4][4][4];
    #pragma unroll
    for (int mt = 0; mt < 4; mt++)
        #pragma unroll
        for (int nt = 0; nt < 4; nt++)
            #pragma unroll
            for (int q = 0; q < 4; q++) c[mt][nt][q] = 0.f;

    #pragma unroll
    for (int c0 = 0; c0 < 128; c0 += 32) {
        #pragma unroll
        for (int i = 0; i < 4; i++) {
            int idx = tid + i * 256;
            int m  = idx >> 3;
            int kk = (idx & 7) << 2;
            float4 a = *(const float4*)(Ab + (long)(m0 + m) * H_ARMA + c0 + kk);
            a.x = fmaxf(a.x, 0.f); a.y = fmaxf(a.y, 0.f);
            a.z = fmaxf(a.z, 0.f); a.w = fmaxf(a.w, 0.f);
            a.x = f2tf32(a.x); a.y = f2tf32(a.y);
            a.z = f2tf32(a.z); a.w = f2tf32(a.w);
            *(float4*)(&sA[m][kk]) = a;
        }
        #pragma unroll
        for (int i = 0; i < 4; i++) {
            int idx = tid + i * 256;
            int kk = idx >> 5;
            int nn = (idx & 31) << 2;
            float4 w = *(const float4*)(Wb + (long)(c0 + kk) * H_ARMA + nn);
            w.x = f2tf32(w.x); w.y = f2tf32(w.y);
            w.z = f2tf32(w.z); w.w = f2tf32(w.w);
            *(float4*)(&sW[kk][nn]) = w;
        }
        __syncthreads();

        #pragma unroll
        for (int ks = 0; ks < 4; ks++) {
            int kb = ks * 8;
            float afr[4][4], bfr[4][2];
            #pragma unroll
            for (int mt = 0; mt < 4; mt++) {
                int r = wm * 64 + mt * 16;
                afr[mt][0] = sA[r + gid    ][kb + tig];
                afr[mt][1] = sA[r + gid + 8][kb + tig];
                afr[mt][2] = sA[r + gid    ][kb + tig + 4];
                afr[mt][3] = sA[r + gid + 8][kb + tig + 4];
            }
            #pragma unroll
            for (int nt = 0; nt < 4; nt++) {
                int cc = wn * 32 + nt * 8 + gid;
                bfr[nt][0] = sW[kb + tig    ][cc];
                bfr[nt][1] = sW[kb + tig + 4][cc];
            }
            #pragma unroll
            for (int mt = 0; mt < 4; mt++)
                #pragma unroll
                for (int nt = 0; nt < 4; nt++)
                    mma_tf32(c[mt][nt], afr[mt], bfr[nt]);
        }
        __syncthreads();
    }

    #pragma unroll
    for (int mt = 0; mt < 4; mt++) {
        #pragma unroll
        for (int nt = 0; nt < 4; nt++) {
            int row = m0 + wm * 64 + mt * 16 + gid;
            int col = wn * 32 + nt * 8 + 2 * tig;
            *(float2*)(Cb + (long)row * H_ARMA + col) =
                make_float2(c[mt][nt][0], c[mt][nt][1]);
            *(float2*)(Cb + (long)(row + 8) * H_ARMA + col) =
                make_float2(c[mt][nt][2], c[mt][nt][3]);
        }
    }
}

// ------------------------- prep: amino CSR + norm + starts + aa feature init -------------------------
__global__ void prep_k(const int* __restrict__ aeiSrc, const int* __restrict__ aeiDst,
                       const int* __restrict__ ab, const float* __restrict__ feat,
                       int* __restrict__ offM, int* __restrict__ listM,
                       float* __restrict__ nrm, int* __restrict__ startp,
                       float* __restrict__ aa)
{
    extern __shared__ int sh[];
    int* cnt  = sh;
    int* cur  = sh + N_AMINO;
    int* part = sh + 2 * N_AMINO;
    int tid = threadIdx.x;

    for (int idx = tid; idx < N_AMINO * F_IN; idx += 1024) {
        int n = idx / F_IN, c = idx - n * F_IN;
        aa[idx] = (c < H) ? 0.f : feat[n * D_AA + (c - H)];
    }

    for (int i = tid; i < N_AMINO; i += 1024) cnt[i] = 0;
    __syncthreads();
    for (int e = tid; e < E_AMINO; e += 1024) atomicAdd(&cnt[aeiDst[e]], 1);
    __syncthreads();
    for (int e = tid; e < E_AMINO; e += 1024) {
        int s = aeiSrc[e], d = aeiDst[e];
        int cs = cnt[s], cd = cnt[d];
        float a = cs > 0 ? rsqrtf((float)cs) : 0.f;
        float c = cd > 0 ? rsqrtf((float)cd) : 0.f;
        nrm[e] = a * c;
    }
    __syncthreads();
    int base = tid * 10;
    int loc[10];
    int s = 0;
    #pragma unroll
    for (int j = 0; j < 10; j++) { loc[j] = cnt[base + j]; s += loc[j]; }
    part[tid] = s;
    __syncthreads();
    for (int off = 1; off < 1024; off <<= 1) {
        int v = part[tid];
        int o = (tid >= off) ? part[tid - off] : 0;
        __syncthreads();
        part[tid] = v + o;
        __syncthreads();
    }
    int run = part[tid] - s;
    #pragma unroll
    for (int j = 0; j < 10; j++) {
        int cc = loc[j];
        cnt[base + j] = run;
        cur[base + j] = run;
        run += cc;
    }
    __syncthreads();
    for (int i = tid; i < N_AMINO; i += 1024) offM[i] = cnt[i];
    if (tid == 0) offM[N_AMINO] = E_AMINO;
    for (int e = tid; e < E_AMINO; e += 1024) {
        int p = atomicAdd(&cur[aeiDst[e]], 1);
        listM[p] = e;
    }
    for (int n = tid; n < N_AMINO; n += 1024) {
        int bv = ab[n];
        int prev = (n == 0) ? -1 : ab[n - 1];
        for (int g = prev + 1; g <= bv; g++) startp[g] = n;
        if (n == N_AMINO - 1)
            for (int g = bv + 1; g <= BGRAPH; g++) startp[g] = N_AMINO;
    }
}

// ------------------------- weight packing -------------------------
__global__ void pack3_k(const float* __restrict__ nw1, const float* __restrict__ nb1,
                        const float* __restrict__ r1,  const float* __restrict__ bb1,
                        const float* __restrict__ nw2, const float* __restrict__ nb2,
                        const float* __restrict__ r2,  const float* __restrict__ bb2,
                        const float* __restrict__ nw3, const float* __restrict__ nb3,
                        const float* __restrict__ r3,  const float* __restrict__ bb3,
                        float* __restrict__ Wp, float* __restrict__ bp)
{
    int layer = blockIdx.y;
    const float *nw, *nb, *root, *b;
    int d_in;
    if (layer == 0)      { nw = nw1; nb = nb1; root = r1; b = bb1; d_in = D_IN; }
    else if (layer == 1) { nw = nw2; nb = nb2; root = r2; b = bb2; d_in = H; }
    else                 { nw = nw3; nb = nb3; root = r3; b = bb3; d_in = H; }
    float* W   = Wp + layer * D_IN * NCOMB;
    float* bpp = bp + layer * NCOMB;

    int idx = blockIdx.x * blockDim.x + threadIdx.x;
    int total = d_in * NCOMB;
    if (idx < total) {
        int i = idx / NCOMB, c = idx % NCOMB;
        float v;
        if (c < 220)      { int d = c / H, o = c % H; v = nw[d * (d_in * H) + i * H + o]; }
        else if (c < 240) { v = nb[i * H + (c - 220)]; }
        else              { v = root[i * H + (c - 240)]; }
        W[idx] = v;
    }
    if (idx < NCOMB) bpp[idx] = (idx < 240) ? 0.f : b[idx - 240];
}

// ------------------------- NNConv edge aggregation (bf16x2, 2 outputs/thread) -----
__global__ void nnconv_edge(const int* __restrict__ ei, const float* __restrict__ ea,
                            const __nv_bfloat16* __restrict__ zb,
                            float* __restrict__ acc)
{
    long idx = (long)blockIdx.x * blockDim.x + threadIdx.x;
    if (idx >= (long)E_ATOMS * (H / 2)) return;
    int e  = (int)(idx / (H / 2));
    int o2 = (int)(idx % (H / 2));
    int o  = o2 * 2;
    int src = ei[e], dst = ei[E_ATOMS + e];
    const __nv_bfloat162* zrow2 =
        (const __nv_bfloat162*)(zb + (long)src * ZCOLS);
    float2 m = __bfloat1622float2(zrow2[110 + o2]);
    const float* eav = ea + (long)e * D_E;
    #pragma unroll
    for (int d = 0; d < D_E; d++) {
        float2 z = __bfloat1622float2(zrow2[d * (H / 2) + o2]);
        float w = eav[d];
        m.x = fmaf(w, z.x, m.x);
        m.y = fmaf(w, z.y, m.y);
    }
    float* dstp = acc + (long)dst * ACOLS + o;
    atomicAdd(dstp,     m.x);
    atomicAdd(dstp + 1, m.y);
}

// ------------------------- atoms -> amino -------------------------
__global__ void atom2aa(const float* __restrict__ acc, const int* __restrict__ lab,
                        float* __restrict__ aa)
{
    long idx = (long)blockIdx.x * blockDim.x + threadIdx.x;
    if (idx >= (long)N_ATOMS * H) return;
    int n = (int)(idx / H), o = (int)(idx % H);
    float v = fmaxf(acc[(long)n * ACOLS + o], 0.f);
    atomicAdd(&aa[lab[n] * F_IN + o], v);
}

// slim ARMA gather: acc = rootterm[t] + gather(nrm * tmp), float4 per thread
__global__ void arma_gather(const float* __restrict__ rt,
                            const int* __restrict__ off, const int* __restrict__ list,
                            const int* __restrict__ aeiSrc, const float* __restrict__ nrm,
                            const float* __restrict__ tmp, float* __restrict__ acc)
{
    int idx = blockIdx.x * blockDim.x + threadIdx.x;
    const int O4 = H_ARMA / 4;
    if (idx >= K_ST * N_AMINO * O4) return;
    int o = (idx & (O4 - 1)) << 2;
    int r = idx >> 5;
    int n = r % N_AMINO;
    int k = r / N_AMINO;

    float4 s = *(const float4*)(rt + 4 * (long)idx);

    long kb = (long)k * N_AMINO;
    int p0 = off[n], p1 = off[n + 1];
    for (int p = p0; p < p1; p++) {
        int e = list[p];
        float nv = nrm[e];
        float4 t = *(const float4*)(tmp + (kb + aeiSrc[e]) * H_ARMA + o);
        s.x = fmaf(nv, t.x, s.x);
        s.y = fmaf(nv, t.y, s.y);
        s.z = fmaf(nv, t.z, s.z);
        s.w = fmaf(nv, t.w, s.w);
    }
    *(float4*)(acc + ((kb + n) * H_ARMA + o)) = s;
}

// ------------------------- fused head: pool + 4 FC layers -------------------------
__global__ void __launch_bounds__(256) head_fused(
        const float* __restrict__ acc, const int* __restrict__ start,
        const float* __restrict__ l1_w, const float* __restrict__ l1_b,
        const float* __restrict__ l2_w, const float* __restrict__ l2_b,
        const float* __restrict__ l3_w, const float* __restrict__ l3_b,
        const float* __restrict__ l4_w, const float* __restrict__ l4_b,
        float* __restrict__ out)
{
    __shared__ float pool[H_ARMA];
    __shared__ float h1[F1];
    __shared__ float h2[F2];
    __shared__ float h3[F3];
    int b = blockIdx.x;
    int tid = threadIdx.x;

    if (tid < H_ARMA) {
        int n0 = start[b], n1 = start[b + 1];
        float s = 0.f;
        for (int n = n0; n < n1; n++) {
            #pragma unroll
            for (int k = 0; k < K_ST; k++)
                s += fmaxf(acc[((long)k * N_AMINO + n) * H_ARMA + tid], 0.f);
        }
        pool[tid] = s * (1.f / 3.f);
    }
    __syncthreads();
    {
        float s = l1_b[tid];
        #pragma unroll 4
        for (int f = 0; f < H_ARMA; f++)
            s = fmaf(pool[f], l1_w[f * F1 + tid], s);
        h1[tid] = fmaxf(s, 0.f);
    }
    __syncthreads();
    if (tid < F2) {
        float s = l2_b[tid];
        #pragma unroll 4
        for (int f = 0; f < F1; f++)
            s = fmaf(h1[f], l2_w[f * F2 + tid], s);
        h2[tid] = fmaxf(s, 0.f);
    }
    __syncthreads();
    if (tid < F3) {
        float s = l3_b[tid];
        #pragma unroll 4
        for (int f = 0; f < F2; f++)
            s = fmaf(h2[f], l3_w[f * F3 + tid], s);
        h3[tid] = fmaxf(s, 0.f);
    }
    __syncthreads();
    if (tid == 0) {
        float s = l4_b[0];
        #pragma unroll
        for (int f = 0; f < F3; f++) s = fmaf(h3[f], l4_w[f], s);
        out[b] = s;
    }
}

// ------------------------- host orchestration -------------------------
static inline int ceil_div(long a, int b) { return (int)((a + b - 1) / b); }

extern "C" void kernel_launch(void* const* d_in, const int* in_sizes, int n_in,
                              void* d_out, int out_size)
{
    const float* x     = (const float*)d_in[0];
    const int*   ei    = (const int*)  d_in[1];
    const float* ea    = (const float*)d_in[2];
    const int*   lab   = (const int*)  d_in[3];
    const float* feat  = (const float*)d_in[4];
    const int*   aei   = (const int*)  d_in[5];
    const int*   ab    = (const int*)  d_in[6];
    const float* nn1_w = (const float*)d_in[7];
    const float* nn1_b = (const float*)d_in[8];
    const float* root1 = (const float*)d_in[9];
    const float* b1    = (const float*)d_in[10];
    const float* nn2_w = (const float*)d_in[11];
    const float* nn2_b = (const float*)d_in[12];
    const float* root2 = (const float*)d_in[13];
    const float* b2    = (const float*)d_in[14];
    const float* nn3_w = (const float*)d_in[15];
    const float* nn3_b = (const float*)d_in[16];
    const float* root3 = (const float*)d_in[17];
    const float* b3    = (const float*)d_in[18];
    const float* arma_init = (const float*)d_in[19];
    const float* arma_w    = (const float*)d_in[20];
    const float* arma_root = (const float*)d_in[21];
    const float* arma_bias = (const float*)d_in[22];
    const float* l1_w = (const float*)d_in[23];
    const float* l1_b = (const float*)d_in[24];
    const float* l2_w = (const float*)d_in[25];
    const float* l2_b = (const float*)d_in[26];
    const float* l3_w = (const float*)d_in[27];
    const float* l3_b = (const float*)d_in[28];
    const float* l4_w = (const float*)d_in[29];
    const float* l4_b = (const float*)d_in[30];

    float *wp, *bp, *aa, *nrm, *tmp, *accA, *accB, *acn1, *acn2, *rtp;
    __nv_bfloat16* zb;
    int *offM, *listM, *startp;
    cudaGetSymbolAddress((void**)&zb,   g_zb);
    cudaGetSymbolAddress((void**)&acn1, g_acn1);
    cudaGetSymbolAddress((void**)&acn2, g_acn2);
    cudaGetSymbolAddress((void**)&wp,   g_wpack);
    cudaGetSymbolAddress((void**)&bp,   g_bpack);
    cudaGetSymbolAddress((void**)&aa,   g_aa);
    cudaGetSymbolAddress((void**)&nrm,  g_norm);
    cudaGetSymbolAddress((void**)&tmp,  g_tmp);
    cudaGetSymbolAddress((void**)&accA, g_accA);
    cudaGetSymbolAddress((void**)&accB, g_accB);
    cudaGetSymbolAddress((void**)&rtp,  g_rootterm);
    cudaGetSymbolAddress((void**)&offM, g_off_am);
    cudaGetSymbolAddress((void**)&listM, g_list_am);
    cudaGetSymbolAddress((void**)&startp, g_start);

    static bool attr_set = false;
    if (!attr_set) {
        cudaFuncSetAttribute(prep_k, cudaFuncAttributeMaxDynamicSharedMemorySize,
                             (2 * N_AMINO + 1024) * sizeof(int));
        attr_set = true;
    }

    const int TB = 256;
    const int* aeiSrc = aei;
    const int* aeiDst = aei + E_AMINO;

    dim3 gN1(ceil_div(N_ATOMS, 128), ceil_div(NCOMB, 64), 1);  // (782, 5)
    int edgeBlocks = ceil_div((long)E_ATOMS * (H / 2), TB);

    // pack + prep
    dim3 gPack(ceil_div(D_IN * NCOMB, TB), 3);
    pack3_k<<<gPack, TB>>>(nn1_w, nn1_b, root1, b1,
                           nn2_w, nn2_b, root2, b2,
                           nn3_w, nn3_b, root3, b3, wp, bp);
    prep_k<<<1, 1024, (2 * N_AMINO + 1024) * sizeof(int)>>>(
        aeiSrc, aeiDst, ab, feat, offM, listM, nrm, startp, aa);

    // NNConv layers
    nnconv_gemm_t<40, 40, 44, 5><<<gN1, 256>>>(x, D_IN, wp, bp, zb, acn1, N_ATOMS, 0);
    nnconv_edge<<<edgeBlocks, TB>>>(ei, ea, zb, acn1);
    nnconv_gemm_t<20, 24, 24, 3><<<gN1, 256>>>(acn1, ACOLS, wp + D_IN * NCOMB, bp + NCOMB,
                                               zb, acn2, N_ATOMS, 1);
    nnconv_edge<<<edgeBlocks, TB>>>(ei, ea, zb, acn2);
    nnconv_gemm_t<20, 24, 24, 3><<<gN1, 256>>>(acn2, ACOLS, wp + 2 * D_IN * NCOMB, bp + 2 * NCOMB,
                                               zb, acn1, N_ATOMS, 1);
    nnconv_edge<<<edgeBlocks, TB>>>(ei, ea, zb, acn1);

    // atoms -> amino
    atom2aa<<<ceil_div((long)N_ATOMS * H, TB), TB>>>(acn1, lab, aa);

    // combined: 21 root terms + 3 t=0 init GEMMs in ONE launch (grid.z = 24)
    dim3 gComb(N_AMINO / 128, H_ARMA / 64, T_LAY * K_ST + K_ST);   // (80, 2, 24)
    arma_gemm28_comb<<<gComb, 256>>>(aa, arma_root, arma_bias, arma_init, rtp, tmp);

    // ARMA: K=3 stacks, T=7 layers (t=0 GEMM already done above)
    dim3 gArma128(N_AMINO / 128, 1, K_ST);            // (80, 1, 3)
    int gatherBlocks = ceil_div(K_ST * N_AMINO * (H_ARMA / 4), TB);
    float* accP = accA;
    float* accN = accB;
    for (int t = 0; t < T_LAY; t++) {
        if (t > 0) {
            arma_gemm128<<<gArma128, 256>>>(
                accP, (long)N_AMINO * H_ARMA,
                arma_w + (long)(t - 1) * K_ST * H_ARMA * H_ARMA, (long)H_ARMA * H_ARMA,
                tmp);
        }
        arma_gather<<<gatherBlocks, TB>>>(
            rtp + (long)t * K_ST * N_AMINO * H_ARMA,
            offM, listM, aeiSrc, nrm, tmp, accN);
        float* t2 = accP; accP = accN; accN = t2;
    }

    // fused head: pool + FC stack
    head_fused<<<BGRAPH, 256>>>(accP, startp,
                                l1_w, l1_b, l2_w, l2_b, l3_w, l3_b, l4_w, l4_b,
                                (float*)d_out);
}